// round 15
// baseline (speedup 1.0000x reference)
#include <cuda_runtime.h>
#include <cuda_bf16.h>
#include <math.h>
#include <stdint.h>

// ---------------- problem constants ----------------
#define B_SZ 8
#define L_SZ 2048
#define DM   768          // d_model
#define DI   1536         // d_inner
#define DS   16           // d_state
#define NROWS (B_SZ * L_SZ)   // 16384

// ---------------- scratch (device globals; no allocation allowed) --------
__device__ float g_xn   [(long)NROWS * DM];        // layernorm output (tf32-rounded)
__device__ float g_xz   [(long)NROWS * 2 * DI];    // in_proj output (xb | z)
__device__ float g_xbc  [(long)NROWS * DI];        // conv+silu output
__device__ float g_xp   [(long)NROWS * 33];        // x_proj output (dt,B,C)
__device__ float g_delta[(long)NROWS * DI];        // softplus delta
__device__ float g_ys   [(long)NROWS * DI];        // scan output * silu(z) (tf32-rounded)
__device__ float g_wa   [(long)2 * DI * DM];       // tf32-rounded in_proj_w
__device__ float g_wb   [(long)DM * DI];           // tf32-rounded out_proj_w

__device__ __forceinline__ float tf32r(float x) {
    asm("cvt.rna.tf32.f32 %0, %0;" : "+f"(x));
    return x;
}

// =====================================================================
// round fp32 -> tf32 (RNA) in bulk (for weights); n multiple of 4
// =====================================================================
__global__ __launch_bounds__(256) void round_tf32_kernel(
    const float* __restrict__ in, float* __restrict__ out, int n4)
{
    int i = blockIdx.x * 256 + threadIdx.x;
    if (i < n4) {
        float4 v = ((const float4*)in)[i];
        v.x = tf32r(v.x); v.y = tf32r(v.y);
        v.z = tf32r(v.z); v.w = tf32r(v.w);
        ((float4*)out)[i] = v;
    }
}

// =====================================================================
// LayerNorm: one block per row of 768 (output tf32-rounded for GEMM1)
// =====================================================================
__global__ __launch_bounds__(256) void ln_kernel(
    const float* __restrict__ x, const float* __restrict__ g,
    const float* __restrict__ b, float* __restrict__ out)
{
    int row = blockIdx.x;
    const float* xr = x + (long)row * DM;
    float* orow = out + (long)row * DM;
    int tid = threadIdx.x;

    float v0 = xr[tid], v1 = xr[tid + 256], v2 = xr[tid + 512];
    float s  = v0 + v1 + v2;
    float s2 = v0 * v0 + v1 * v1 + v2 * v2;

    __shared__ float red[16];
    #pragma unroll
    for (int o = 16; o; o >>= 1) {
        s  += __shfl_xor_sync(0xffffffffu, s,  o);
        s2 += __shfl_xor_sync(0xffffffffu, s2, o);
    }
    int w = tid >> 5, lane = tid & 31;
    if (lane == 0) { red[w] = s; red[w + 8] = s2; }
    __syncthreads();
    if (tid == 0) {
        float S = 0.f, S2 = 0.f;
        #pragma unroll
        for (int i = 0; i < 8; i++) { S += red[i]; S2 += red[i + 8]; }
        red[0] = S; red[8] = S2;
    }
    __syncthreads();
    float mu  = red[0] * (1.f / DM);
    float var = red[8] * (1.f / DM) - mu * mu;
    float rs  = rsqrtf(var + 1e-5f);

    orow[tid]       = tf32r((v0 - mu) * rs * g[tid]       + b[tid]);
    orow[tid + 256] = tf32r((v1 - mu) * rs * g[tid + 256] + b[tid + 256]);
    orow[tid + 512] = tf32r((v2 - mu) * rs * g[tid + 512] + b[tid + 512]);
}

// =====================================================================
// TF32 tensor-core GEMM (NT): C[M,N] = A[M,K] @ B[N,K]^T (+ residual)
// 256x128 CTA tile, 8 warps as 4(M)x2(N), warp tile 64x64 = 4x8
// m16n8k8 per k8-step. Cuts smem-crossbar fragment traffic per MAC
// 1.5x vs 128x128 (A re-read x2 instead of x4) — crossbar was the
// measured ceiling. STATIC shared memory (108KB) — the dynamic-smem +
// cudaFuncSetAttribute path correlates 4/4 with container deaths;
// static smem at 74KB is proven working (R12/R13).
// Fragment loads via ldmatrix x4 (A and B). M%256==0, N%128==0, K%32==0.
// =====================================================================
#define CP16(dst, src) asm volatile("cp.async.cg.shared.global [%0], [%1], 16;" :: "r"(dst), "l"(src))
#define CP_COMMIT()    asm volatile("cp.async.commit_group;")
#define CP_WAIT0()     asm volatile("cp.async.wait_group 0;")

template <bool ADD_RES>
__global__ __launch_bounds__(256, 1) void tf32_gemm_nt(
    const float* __restrict__ A, const float* __restrict__ Bm,
    const float* __restrict__ Res, float* __restrict__ C,
    int M, int N, int K)
{
    __shared__ float As[2][256 * 36];   // 73728 B
    __shared__ float Bs[2][128 * 36];   // 36864 B   (total 108 KB static)
    const int A_STAGE = 256 * 36;   // floats
    const int B_STAGE = 128 * 36;

    const int bm = blockIdx.y * 256;
    const int bn = blockIdx.x * 128;
    const int tid = threadIdx.x;
    const int w    = tid >> 5, lane = tid & 31;
    const int wm   = w >> 1;       // 0..3  (M direction, 64 rows each)
    const int wn   = w & 1;        // 0..1  (N direction, 64 cols each)
    const int g    = lane >> 2;    // group id 0..7
    const int tg   = lane & 3;     // thread-in-group

    // ldmatrix per-thread address components (floats)
    const int tr  = lane & 7;      // row within an 8-row matrix
    const int sel = lane >> 3;     // which of the 4 matrices
    // A .x4: m0=rows r..r+7 @k, m1=rows+8 @k, m2=rows @k+4, m3=rows+8 @k+4
    // (identical mapping to the R13-passing kernel)
    const int a_off = (tr + ((sel & 1) << 3)) * 36 + ((sel >> 1) << 2);
    // B .x4 covering an nt-pair: m0=cols c..c+7 @k, m1=@k+4, m2=cols+8 @k, m3=@k+4
    const int b_off = (tr + ((sel >> 1) << 3)) * 36 + ((sel & 1) << 2);

    // gmem->smem staging: A 8 rows/thread, B 4 rows/thread (float4 each)
    const int ra = tid >> 3;          // 0..31
    const int kq = (tid & 7) * 4;     // k offset in floats
    const float* Ag = A  + (long)(bm + ra) * K + kq;
    const float* Bg = Bm + (long)(bn + ra) * K + kq;

    const uint32_t sA = (uint32_t)__cvta_generic_to_shared(&As[0][0]);
    const uint32_t sB = (uint32_t)__cvta_generic_to_shared(&Bs[0][0]);

    #pragma unroll
    for (int i = 0; i < 8; i++)
        CP16(sA + (uint32_t)(((ra + 32 * i) * 36 + kq) * 4), Ag + (long)32 * i * K);
    #pragma unroll
    for (int i = 0; i < 4; i++)
        CP16(sB + (uint32_t)(((ra + 32 * i) * 36 + kq) * 4), Bg + (long)32 * i * K);
    CP_COMMIT();

    float acc[4][8][4] = {};
    const int KT = K >> 5;
    int buf = 0;

    CP_WAIT0();
    __syncthreads();

    for (int kt = 0; kt < KT; ++kt) {
        if (kt + 1 < KT) {
            const int nb = buf ^ 1;
            const float* An = Ag + (kt + 1) * 32;
            const float* Bn = Bg + (kt + 1) * 32;
            #pragma unroll
            for (int i = 0; i < 8; i++)
                CP16(sA + (uint32_t)((nb * A_STAGE + (ra + 32 * i) * 36 + kq) * 4), An + (long)32 * i * K);
            #pragma unroll
            for (int i = 0; i < 4; i++)
                CP16(sB + (uint32_t)((nb * B_STAGE + (ra + 32 * i) * 36 + kq) * 4), Bn + (long)32 * i * K);
            CP_COMMIT();
        }

        const uint32_t aBase = sA + (uint32_t)(buf * A_STAGE * 4);
        const uint32_t bBase = sB + (uint32_t)(buf * B_STAGE * 4);

        #pragma unroll
        for (int s = 0; s < 4; s++) {
            uint32_t af[4][4], bf[4][4];
            #pragma unroll
            for (int mt = 0; mt < 4; mt++) {
                uint32_t addr = aBase
                    + (uint32_t)((((wm * 64 + mt * 16) * 36) + s * 8 + a_off) * 4);
                asm volatile(
                    "ldmatrix.sync.aligned.m8n8.x4.shared.b16 {%0,%1,%2,%3}, [%4];"
                    : "=r"(af[mt][0]), "=r"(af[mt][1]),
                      "=r"(af[mt][2]), "=r"(af[mt][3])
                    : "r"(addr));
            }
            #pragma unroll
            for (int p = 0; p < 4; p++) {   // nt-pair p covers nt=2p, 2p+1
                uint32_t addr = bBase
                    + (uint32_t)((((wn * 64 + p * 16) * 36) + s * 8 + b_off) * 4);
                asm volatile(
                    "ldmatrix.sync.aligned.m8n8.x4.shared.b16 {%0,%1,%2,%3}, [%4];"
                    : "=r"(bf[p][0]), "=r"(bf[p][1]),
                      "=r"(bf[p][2]), "=r"(bf[p][3])
                    : "r"(addr));
            }
            #pragma unroll
            for (int mt = 0; mt < 4; mt++)
                #pragma unroll
                for (int nt = 0; nt < 8; nt++)
                    asm volatile(
                        "mma.sync.aligned.m16n8k8.row.col.f32.tf32.tf32.f32 "
                        "{%0,%1,%2,%3}, {%4,%5,%6,%7}, {%8,%9}, {%0,%1,%2,%3};"
                        : "+f"(acc[mt][nt][0]), "+f"(acc[mt][nt][1]),
                          "+f"(acc[mt][nt][2]), "+f"(acc[mt][nt][3])
                        : "r"(af[mt][0]), "r"(af[mt][1]), "r"(af[mt][2]), "r"(af[mt][3]),
                          "r"(bf[nt >> 1][(nt & 1) * 2]), "r"(bf[nt >> 1][(nt & 1) * 2 + 1]));
        }

        if (kt + 1 < KT) {
            CP_WAIT0();
            __syncthreads();
            buf ^= 1;
        }
    }

    #pragma unroll
    for (int mt = 0; mt < 4; mt++) {
        #pragma unroll
        for (int nt = 0; nt < 8; nt++) {
            int row = bm + wm * 64 + mt * 16 + g;
            int col = bn + wn * 64 + nt * 8 + tg * 2;
            long i0 = (long)row * N + col;
            long i1 = (long)(row + 8) * N + col;
            float2 r0 = make_float2(acc[mt][nt][0], acc[mt][nt][1]);
            float2 r1 = make_float2(acc[mt][nt][2], acc[mt][nt][3]);
            if (ADD_RES) {
                float2 e0 = *(const float2*)&Res[i0];
                float2 e1 = *(const float2*)&Res[i1];
                r0.x += e0.x; r0.y += e0.y;
                r1.x += e1.x; r1.y += e1.y;
            }
            *(float2*)&C[i0] = r0;
            *(float2*)&C[i1] = r1;
        }
    }
}

// =====================================================================
// Causal depthwise conv (width 4) + bias + silu.
// =====================================================================
__global__ __launch_bounds__(256) void conv_kernel(
    const float* __restrict__ xz, const float* __restrict__ cw,
    const float* __restrict__ cb, float* __restrict__ out)
{
    int d  = blockIdx.x * 256 + threadIdx.x;  // 0..1535
    int b  = blockIdx.z;
    int l0 = blockIdx.y * 16;

    float w0 = cw[d * 4 + 0], w1 = cw[d * 4 + 1];
    float w2 = cw[d * 4 + 2], w3 = cw[d * 4 + 3];
    float bias = cb[d];

    const float* base = xz + ((long)b * L_SZ) * (2 * DI) + d;
    float v0 = (l0 >= 3) ? base[(long)(l0 - 3) * (2 * DI)] : 0.f;
    float v1 = (l0 >= 2) ? base[(long)(l0 - 2) * (2 * DI)] : 0.f;
    float v2 = (l0 >= 1) ? base[(long)(l0 - 1) * (2 * DI)] : 0.f;

    float* op = out + ((long)b * L_SZ + l0) * DI + d;
    #pragma unroll
    for (int i = 0; i < 16; i++) {
        float v3 = base[(long)(l0 + i) * (2 * DI)];
        float a = fmaf(w0, v0, fmaf(w1, v1, fmaf(w2, v2, fmaf(w3, v3, bias))));
        float sv = a * __fdividef(1.f, 1.f + __expf(-a));   // silu
        op[(long)i * DI] = sv;
        v0 = v1; v1 = v2; v2 = v3;
    }
}

// =====================================================================
// x_proj: xp[row, 0..32] = xbc[row,:] @ Wxp^T  (Wxp is (33,1536))
// plus delta[row, d] = softplus(xp[row,0]*dt_w[d] + dt_b[d])
// 8 rows/block; all inner-loop loads are float4 (LDS.128/LDG.128).
// =====================================================================
__global__ __launch_bounds__(256) void xproj_kernel(
    const float* __restrict__ xbc, const float* __restrict__ W,
    const float* __restrict__ dtw, const float* __restrict__ dtb,
    float* __restrict__ xp, float* __restrict__ delta)
{
    __shared__ float rs[8][DI];   // exactly 48KB
    int row0 = blockIdx.x * 8;
    int tid = threadIdx.x;

    #pragma unroll
    for (int r = 0; r < 8; r++)
        for (int k = tid; k < DI / 4; k += 256)
            *(float4*)&rs[r][k * 4] = ((const float4*)(xbc + (long)(row0 + r) * DI))[k];
    __syncthreads();

    int w = tid >> 5, lane = tid & 31;
    for (int n = w; n < 33; n += 8) {
        const float4* wr = (const float4*)(W + (long)n * DI);
        float a[8];
        #pragma unroll
        for (int r = 0; r < 8; r++) a[r] = 0.f;
        #pragma unroll 4
        for (int i = lane; i < DI / 4; i += 32) {   // 12 iterations
            float4 wv = wr[i];
            #pragma unroll
            for (int r = 0; r < 8; r++) {
                float4 rv = *(const float4*)&rs[r][i * 4];
                a[r] = fmaf(wv.x, rv.x, a[r]);
                a[r] = fmaf(wv.y, rv.y, a[r]);
                a[r] = fmaf(wv.z, rv.z, a[r]);
                a[r] = fmaf(wv.w, rv.w, a[r]);
            }
        }
        #pragma unroll
        for (int o = 16; o; o >>= 1) {
            #pragma unroll
            for (int r = 0; r < 8; r++)
                a[r] += __shfl_xor_sync(0xffffffffu, a[r], o);
        }
        if (lane == 0) {
            #pragma unroll
            for (int r = 0; r < 8; r++)
                xp[((long)row0 + r) * 33 + n] = a[r];
        }
    }
    __syncthreads();   // orders the global xp writes within the block

    #pragma unroll
    for (int r = 0; r < 8; r++) {
        float xp0 = xp[((long)(row0 + r)) * 33];
        for (int dd = tid; dd < DI; dd += 256) {
            float v  = fmaf(xp0, dtw[dd], dtb[dd]);
            float sp = (v > 20.f) ? v : log1pf(__expf(v));
            delta[((long)(row0 + r)) * DI + dd] = sp;
        }
    }
}

// =====================================================================
// Selective scan, fused with D*x, silu(z) gate. Output tf32-rounded.
// 8 threads per channel (2 states each), 256-thread blocks, grid (48,8).
// =====================================================================
__global__ __launch_bounds__(256) void scan_kernel(
    const float* __restrict__ xbc, const float* __restrict__ xz,
    const float* __restrict__ xp, const float* __restrict__ delta,
    const float* __restrict__ Alog, const float* __restrict__ Dv,
    float* __restrict__ ys)
{
    const int b   = blockIdx.y;
    const int d0  = blockIdx.x * 32;
    const int tid = threadIdx.x;
    const int c   = tid >> 3;   // channel-local 0..31
    const int sg  = tid & 7;    // state group (2 states each)
    const int d   = d0 + c;
    const int n   = sg * 2;

    float a0 = -__expf(Alog[d * DS + n + 0]);
    float a1 = -__expf(Alog[d * DS + n + 1]);
    float dd = Dv[d];

    __shared__ float x_s [32][32];
    __shared__ float z_s [32][32];
    __shared__ float dl_s[32][32];
    __shared__ float bc_s[32][32];   // cols 0..15 = B', 16..31 = C'
    __shared__ float y_s [32][32];

    float h0 = 0.f, h1 = 0.f;
    const long rb = (long)b * L_SZ;

    for (int t0 = 0; t0 < L_SZ; t0 += 32) {
        #pragma unroll
        for (int i = tid; i < 1024; i += 256) {
            int t = i >> 5, cc = i & 31;
            long row = rb + t0 + t;
            x_s [t][cc] = xbc  [row * DI + d0 + cc];
            dl_s[t][cc] = delta[row * DI + d0 + cc];
            z_s [t][cc] = xz   [row * (2 * DI) + DI + d0 + cc];
            bc_s[t][cc] = xp   [row * 33 + 1 + cc];
        }
        __syncthreads();

        #pragma unroll 8
        for (int t = 0; t < 32; t++) {
            float dl   = dl_s[t][c];
            float xv   = x_s[t][c];
            float coef = dl * xv;
            float e0 = __expf(dl * a0), e1 = __expf(dl * a1);
            h0 = fmaf(e0, h0, coef * bc_s[t][n + 0]);
            h1 = fmaf(e1, h1, coef * bc_s[t][n + 1]);
            float y = h0 * bc_s[t][16 + n + 0] + h1 * bc_s[t][16 + n + 1];
            y += __shfl_xor_sync(0xffffffffu, y, 1);
            y += __shfl_xor_sync(0xffffffffu, y, 2);
            y += __shfl_xor_sync(0xffffffffu, y, 4);
            if (sg == 0) {
                float yt = fmaf(dd, xv, y);
                float zv = z_s[t][c];
                float sz = __fdividef(zv, 1.f + __expf(-zv));  // silu(z)
                y_s[t][c] = yt * sz;
            }
        }
        __syncthreads();

        #pragma unroll
        for (int i = tid; i < 1024; i += 256) {
            int t = i >> 5, cc = i & 31;
            ys[(rb + t0 + t) * DI + d0 + cc] = tf32r(y_s[t][cc]);
        }
        // safe without an extra sync: staging writes x/dl/z/bc only and the
        // post-staging __syncthreads orders them before the step loop; the
        // writeout reads y_s only, which staging never touches.
    }
}

// =====================================================================
// launcher
// =====================================================================
extern "C" void kernel_launch(void* const* d_in, const int* in_sizes, int n_in,
                              void* d_out, int out_size)
{
    const float* x    = (const float*)d_in[0];
    const float* ln_g = (const float*)d_in[1];
    const float* ln_b = (const float*)d_in[2];
    const float* Win  = (const float*)d_in[3];   // (3072, 768)
    const float* cw   = (const float*)d_in[4];   // (1536, 1, 4)
    const float* cb   = (const float*)d_in[5];   // (1536,)
    const float* Wxp  = (const float*)d_in[6];   // (33, 1536)
    const float* dtw  = (const float*)d_in[7];   // (1536, 1)
    const float* dtb  = (const float*)d_in[8];   // (1536,)
    const float* Alog = (const float*)d_in[9];   // (1536, 16)
    const float* Dv   = (const float*)d_in[10];  // (1536,)
    const float* Wout = (const float*)d_in[11];  // (768, 1536)
    float* out = (float*)d_out;

    float *xn, *xz, *xbc, *xp, *dl, *ys, *wa, *wb;
    cudaGetSymbolAddress((void**)&xn,  g_xn);
    cudaGetSymbolAddress((void**)&xz,  g_xz);
    cudaGetSymbolAddress((void**)&xbc, g_xbc);
    cudaGetSymbolAddress((void**)&xp,  g_xp);
    cudaGetSymbolAddress((void**)&dl,  g_delta);
    cudaGetSymbolAddress((void**)&ys,  g_ys);
    cudaGetSymbolAddress((void**)&wa,  g_wa);
    cudaGetSymbolAddress((void**)&wb,  g_wb);

    // 0) round weights to tf32 (RNA)
    {
        int n4a = (2 * DI * DM) / 4;
        round_tf32_kernel<<<(n4a + 255) / 256, 256>>>(Win, wa, n4a);
        int n4b = (DM * DI) / 4;
        round_tf32_kernel<<<(n4b + 255) / 256, 256>>>(Wout, wb, n4b);
    }

    // 1) LayerNorm (tf32-rounded output)
    ln_kernel<<<NROWS, 256>>>(x, ln_g, ln_b, xn);

    // 2) in_proj: xz = xn @ Win^T   (16384 x 3072, K=768) — tensor cores
    tf32_gemm_nt<false><<<dim3(3072 / 128, NROWS / 256), 256>>>(
        xn, wa, nullptr, xz, NROWS, 2 * DI, DM);

    // 3) causal depthwise conv + silu
    conv_kernel<<<dim3(DI / 256, L_SZ / 16, B_SZ), 256>>>(xz, cw, cb, xbc);

    // 4) x_proj + delta (8 rows/block, float4 path)
    xproj_kernel<<<NROWS / 8, 256>>>(xbc, Wxp, dtw, dtb, xp, dl);

    // 5) selective scan fused with D*x and silu(z) gate (8 thr/channel)
    scan_kernel<<<dim3(DI / 32, B_SZ), 256>>>(xbc, xz, xp, dl, Alog, Dv, ys);

    // 6) out_proj + residual: out = ys @ Wout^T + x — tensor cores
    tf32_gemm_nt<true><<<dim3(DM / 128, NROWS / 256), 256>>>(
        ys, wb, x, out, NROWS, DM, DI);
}

// round 16
// speedup vs baseline: 1.0835x; 1.0835x over previous
#include <cuda_runtime.h>
#include <cuda_bf16.h>
#include <math.h>
#include <stdint.h>

// ---------------- problem constants ----------------
#define B_SZ 8
#define L_SZ 2048
#define DM   768          // d_model
#define DI   1536         // d_inner
#define DS   16           // d_state
#define NROWS (B_SZ * L_SZ)   // 16384

// ---------------- scratch (device globals; no allocation allowed) --------
__device__ float g_xn   [(long)NROWS * DM];        // layernorm output (tf32-rounded)
__device__ float g_xz   [(long)NROWS * 2 * DI];    // in_proj output (xb | z)
__device__ float g_xbc  [(long)NROWS * DI];        // conv+silu output
__device__ float g_xp   [(long)NROWS * 33];        // x_proj output (dt,B,C)
__device__ float g_ys   [(long)NROWS * DI];        // scan output * silu(z) (tf32-rounded)
__device__ float g_wa   [(long)2 * DI * DM];       // tf32-rounded in_proj_w
__device__ float g_wb   [(long)DM * DI];           // tf32-rounded out_proj_w

__device__ __forceinline__ float tf32r(float x) {
    asm("cvt.rna.tf32.f32 %0, %0;" : "+f"(x));
    return x;
}

// =====================================================================
// round fp32 -> tf32 (RNA) in bulk (for weights); n multiple of 4
// =====================================================================
__global__ __launch_bounds__(256) void round_tf32_kernel(
    const float* __restrict__ in, float* __restrict__ out, int n4)
{
    int i = blockIdx.x * 256 + threadIdx.x;
    if (i < n4) {
        float4 v = ((const float4*)in)[i];
        v.x = tf32r(v.x); v.y = tf32r(v.y);
        v.z = tf32r(v.z); v.w = tf32r(v.w);
        ((float4*)out)[i] = v;
    }
}

// =====================================================================
// LayerNorm: one block per row of 768 (output tf32-rounded for GEMM1)
// =====================================================================
__global__ __launch_bounds__(256) void ln_kernel(
    const float* __restrict__ x, const float* __restrict__ g,
    const float* __restrict__ b, float* __restrict__ out)
{
    int row = blockIdx.x;
    const float* xr = x + (long)row * DM;
    float* orow = out + (long)row * DM;
    int tid = threadIdx.x;

    float v0 = xr[tid], v1 = xr[tid + 256], v2 = xr[tid + 512];
    float s  = v0 + v1 + v2;
    float s2 = v0 * v0 + v1 * v1 + v2 * v2;

    __shared__ float red[16];
    #pragma unroll
    for (int o = 16; o; o >>= 1) {
        s  += __shfl_xor_sync(0xffffffffu, s,  o);
        s2 += __shfl_xor_sync(0xffffffffu, s2, o);
    }
    int w = tid >> 5, lane = tid & 31;
    if (lane == 0) { red[w] = s; red[w + 8] = s2; }
    __syncthreads();
    if (tid == 0) {
        float S = 0.f, S2 = 0.f;
        #pragma unroll
        for (int i = 0; i < 8; i++) { S += red[i]; S2 += red[i + 8]; }
        red[0] = S; red[8] = S2;
    }
    __syncthreads();
    float mu  = red[0] * (1.f / DM);
    float var = red[8] * (1.f / DM) - mu * mu;
    float rs  = rsqrtf(var + 1e-5f);

    orow[tid]       = tf32r((v0 - mu) * rs * g[tid]       + b[tid]);
    orow[tid + 256] = tf32r((v1 - mu) * rs * g[tid + 256] + b[tid + 256]);
    orow[tid + 512] = tf32r((v2 - mu) * rs * g[tid + 512] + b[tid + 512]);
}

// =====================================================================
// TF32 tensor-core GEMM (NT): C[M,N] = A[M,K] @ B[N,K]^T (+ residual)
// EXACT R13 kernel (best measured: GEMM1=457us, 2 CTA/SM): 128x128x32
// tiles, 8 warps 2(M)x4(N), warp tile 64x32, ldmatrix fragment loads,
// stride-36 smem, cp.async double buffering. R15 taught: bigger tiles
// lose CTA-overlap and regress — do not re-tile this.
// =====================================================================
#define CP16(dst, src) asm volatile("cp.async.cg.shared.global [%0], [%1], 16;" :: "r"(dst), "l"(src))
#define CP_COMMIT()    asm volatile("cp.async.commit_group;")
#define CP_WAIT0()     asm volatile("cp.async.wait_group 0;")

template <bool ADD_RES>
__global__ __launch_bounds__(256) void tf32_gemm_nt(
    const float* __restrict__ A, const float* __restrict__ Bm,
    const float* __restrict__ Res, float* __restrict__ C,
    int M, int N, int K)
{
    __shared__ float As[2][128 * 36];
    __shared__ float Bs[2][128 * 36];

    const int bm = blockIdx.y * 128;
    const int bn = blockIdx.x * 128;
    const int tid = threadIdx.x;
    const int w    = tid >> 5, lane = tid & 31;
    const int wm   = w & 1;        // 0..1  (M direction, 64 each)
    const int wn   = w >> 1;       // 0..3  (N direction, 32 each)
    const int g    = lane >> 2;    // group id 0..7
    const int tg   = lane & 3;     // thread-in-group

    // ldmatrix per-thread address components
    const int tr  = lane & 7;      // row within an 8-row matrix
    const int sel = lane >> 3;     // which of the 4 (x4) / 2 (x2) matrices
    const int a_off = (tr + ((sel & 1) << 3)) * 36 + ((sel >> 1) << 2);
    const int b_off = tr * 36 + ((sel & 1) << 2);

    const int ra = tid >> 3;          // 0..31 (row within 32-row slab)
    const int kq = (tid & 7) * 4;     // k offset in floats (0,4,..,28)
    const float* Ag = A  + (long)(bm + ra) * K + kq;
    const float* Bg = Bm + (long)(bn + ra) * K + kq;

    const uint32_t sA = (uint32_t)__cvta_generic_to_shared(&As[0][0]);
    const uint32_t sB = (uint32_t)__cvta_generic_to_shared(&Bs[0][0]);

    #pragma unroll
    for (int i = 0; i < 4; i++) {
        CP16(sA + (uint32_t)(((ra + 32 * i) * 36 + kq) * 4), Ag + (long)32 * i * K);
        CP16(sB + (uint32_t)(((ra + 32 * i) * 36 + kq) * 4), Bg + (long)32 * i * K);
    }
    CP_COMMIT();

    float acc[4][4][4] = {};
    const int KT = K >> 5;
    int buf = 0;

    CP_WAIT0();
    __syncthreads();

    for (int kt = 0; kt < KT; ++kt) {
        if (kt + 1 < KT) {
            const int nb = buf ^ 1;
            const float* An = Ag + (kt + 1) * 32;
            const float* Bn = Bg + (kt + 1) * 32;
            #pragma unroll
            for (int i = 0; i < 4; i++) {
                CP16(sA + (uint32_t)((nb * 4608 + (ra + 32 * i) * 36 + kq) * 4), An + (long)32 * i * K);
                CP16(sB + (uint32_t)((nb * 4608 + (ra + 32 * i) * 36 + kq) * 4), Bn + (long)32 * i * K);
            }
            CP_COMMIT();
        }

        const uint32_t aBase = sA + (uint32_t)(buf * 4608 * 4);
        const uint32_t bBase = sB + (uint32_t)(buf * 4608 * 4);

        #pragma unroll
        for (int s = 0; s < 4; s++) {
            uint32_t af[4][4], bf[4][2];
            #pragma unroll
            for (int mt = 0; mt < 4; mt++) {
                uint32_t addr = aBase
                    + (uint32_t)((((wm * 64 + mt * 16) * 36) + s * 8 + a_off) * 4);
                asm volatile(
                    "ldmatrix.sync.aligned.m8n8.x4.shared.b16 {%0,%1,%2,%3}, [%4];"
                    : "=r"(af[mt][0]), "=r"(af[mt][1]),
                      "=r"(af[mt][2]), "=r"(af[mt][3])
                    : "r"(addr));
            }
            #pragma unroll
            for (int nt = 0; nt < 4; nt++) {
                uint32_t addr = bBase
                    + (uint32_t)((((wn * 32 + nt * 8) * 36) + s * 8 + b_off) * 4);
                asm volatile(
                    "ldmatrix.sync.aligned.m8n8.x2.shared.b16 {%0,%1}, [%2];"
                    : "=r"(bf[nt][0]), "=r"(bf[nt][1])
                    : "r"(addr));
            }
            #pragma unroll
            for (int mt = 0; mt < 4; mt++)
                #pragma unroll
                for (int nt = 0; nt < 4; nt++)
                    asm volatile(
                        "mma.sync.aligned.m16n8k8.row.col.f32.tf32.tf32.f32 "
                        "{%0,%1,%2,%3}, {%4,%5,%6,%7}, {%8,%9}, {%0,%1,%2,%3};"
                        : "+f"(acc[mt][nt][0]), "+f"(acc[mt][nt][1]),
                          "+f"(acc[mt][nt][2]), "+f"(acc[mt][nt][3])
                        : "r"(af[mt][0]), "r"(af[mt][1]), "r"(af[mt][2]), "r"(af[mt][3]),
                          "r"(bf[nt][0]), "r"(bf[nt][1]));
        }

        if (kt + 1 < KT) {
            CP_WAIT0();
            __syncthreads();
            buf ^= 1;
        }
    }

    #pragma unroll
    for (int mt = 0; mt < 4; mt++) {
        #pragma unroll
        for (int nt = 0; nt < 4; nt++) {
            int row = bm + wm * 64 + mt * 16 + g;
            int col = bn + wn * 32 + nt * 8 + tg * 2;
            long i0 = (long)row * N + col;
            long i1 = (long)(row + 8) * N + col;
            float2 r0 = make_float2(acc[mt][nt][0], acc[mt][nt][1]);
            float2 r1 = make_float2(acc[mt][nt][2], acc[mt][nt][3]);
            if (ADD_RES) {
                float2 e0 = *(const float2*)&Res[i0];
                float2 e1 = *(const float2*)&Res[i1];
                r0.x += e0.x; r0.y += e0.y;
                r1.x += e1.x; r1.y += e1.y;
            }
            *(float2*)&C[i0] = r0;
            *(float2*)&C[i1] = r1;
        }
    }
}

// =====================================================================
// FUSED conv + silu + x_proj.
// Per block: 8 rows. Conv(width 4, causal) computed straight from g_xz
// (3-row halo; zero-guard only when l0==0), result kept in smem AND
// written once to g_xbc (float4). Then the 33-way dot products.
// Eliminates the separate conv kernel (one 100MB read + a launch) and
// the delta tail (delta moved into scan: kills 200MB of DRAM traffic).
// =====================================================================
__global__ __launch_bounds__(256) void xproj_kernel(
    const float* __restrict__ xz, const float* __restrict__ cw,
    const float* __restrict__ cb, const float* __restrict__ W,
    float* __restrict__ xbc, float* __restrict__ xp)
{
    __shared__ float rs[8][DI];   // conv+silu output, exactly 48KB
    int row0 = blockIdx.x * 8;
    int tid = threadIdx.x;
    const bool at_start = (row0 % L_SZ) == 0;   // l0 == 0: halo is zeros

    // conv: thread owns channels c = tid + 256k, all 8 rows
    for (int c = tid; c < DI; c += 256) {
        float4 wv = ((const float4*)cw)[c];     // (DI,1,4) row-major
        float bias = cb[c];
        const float* base = xz + (long)row0 * (2 * DI) + c;
        float v0 = at_start ? 0.f : base[-3 * (2 * DI)];
        float v1 = at_start ? 0.f : base[-2 * (2 * DI)];
        float v2 = at_start ? 0.f : base[-1 * (2 * DI)];
        #pragma unroll
        for (int r = 0; r < 8; r++) {
            float v3 = base[(long)r * (2 * DI)];
            float a = fmaf(wv.x, v0, fmaf(wv.y, v1, fmaf(wv.z, v2, fmaf(wv.w, v3, bias))));
            float sv = a * __fdividef(1.f, 1.f + __expf(-a));   // silu
            rs[r][c] = sv;
            v0 = v1; v1 = v2; v2 = v3;
        }
    }
    __syncthreads();

    // write xbc once, coalesced float4 from smem
    for (int k = tid; k < 8 * (DI / 4); k += 256) {
        int r = k / (DI / 4), c4 = k % (DI / 4);
        ((float4*)(xbc + (long)(row0 + r) * DI))[c4] = *(const float4*)&rs[r][c4 * 4];
    }

    // dots: 8 warps split the 33 outputs; float4 inner loop
    int w = tid >> 5, lane = tid & 31;
    for (int n = w; n < 33; n += 8) {
        const float4* wr = (const float4*)(W + (long)n * DI);
        float a[8];
        #pragma unroll
        for (int r = 0; r < 8; r++) a[r] = 0.f;
        #pragma unroll 4
        for (int i = lane; i < DI / 4; i += 32) {   // 12 iterations
            float4 wv = wr[i];
            #pragma unroll
            for (int r = 0; r < 8; r++) {
                float4 rv = *(const float4*)&rs[r][i * 4];
                a[r] = fmaf(wv.x, rv.x, a[r]);
                a[r] = fmaf(wv.y, rv.y, a[r]);
                a[r] = fmaf(wv.z, rv.z, a[r]);
                a[r] = fmaf(wv.w, rv.w, a[r]);
            }
        }
        #pragma unroll
        for (int o = 16; o; o >>= 1) {
            #pragma unroll
            for (int r = 0; r < 8; r++)
                a[r] += __shfl_xor_sync(0xffffffffu, a[r], o);
        }
        if (lane == 0) {
            #pragma unroll
            for (int r = 0; r < 8; r++)
                xp[((long)row0 + r) * 33 + n] = a[r];
        }
    }
}

// =====================================================================
// Selective scan, fused with delta=softplus(xp0*dtw+dtb), D*x, silu(z).
// delta computed in the staging loop (channel fixed per thread -> dtw/
// dtb in registers): replaces the 200MB delta tensor with ~2 MUFU per
// staged element. 8 threads/channel (2 states each), grid (48,8).
// Output tf32-rounded for GEMM2.
// =====================================================================
__global__ __launch_bounds__(256) void scan_kernel(
    const float* __restrict__ xbc, const float* __restrict__ xz,
    const float* __restrict__ xp, const float* __restrict__ dtw,
    const float* __restrict__ dtb, const float* __restrict__ Alog,
    const float* __restrict__ Dv, float* __restrict__ ys)
{
    const int b   = blockIdx.y;
    const int d0  = blockIdx.x * 32;
    const int tid = threadIdx.x;
    const int c   = tid >> 3;   // channel-local 0..31
    const int sg  = tid & 7;    // state group (2 states each)
    const int d   = d0 + c;
    const int n   = sg * 2;

    float a0 = -__expf(Alog[d * DS + n + 0]);
    float a1 = -__expf(Alog[d * DS + n + 1]);
    float dd = Dv[d];

    // staging channel for this thread is fixed: cs = tid & 31
    const int cs = tid & 31;
    const float dtwc = dtw[d0 + cs];
    const float dtbc = dtb[d0 + cs];

    __shared__ float x_s [32][32];
    __shared__ float z_s [32][32];
    __shared__ float dl_s[32][32];
    __shared__ float bc_s[32][32];   // cols 0..15 = B', 16..31 = C'
    __shared__ float y_s [32][32];

    float h0 = 0.f, h1 = 0.f;
    const long rb = (long)b * L_SZ;

    for (int t0 = 0; t0 < L_SZ; t0 += 32) {
        #pragma unroll
        for (int i = tid; i < 1024; i += 256) {
            int t = i >> 5;               // cc == cs for all i of this thread
            long row = rb + t0 + t;
            x_s [t][cs] = xbc[row * DI + d0 + cs];
            z_s [t][cs] = xz [row * (2 * DI) + DI + d0 + cs];
            bc_s[t][cs] = xp [row * 33 + 1 + cs];
            float xp0 = __ldg(&xp[row * 33]);            // broadcast load
            float v   = fmaf(xp0, dtwc, dtbc);
            dl_s[t][cs] = (v > 15.f) ? v : __logf(1.f + __expf(v));  // softplus
        }
        __syncthreads();

        #pragma unroll 8
        for (int t = 0; t < 32; t++) {
            float dl   = dl_s[t][c];
            float xv   = x_s[t][c];
            float coef = dl * xv;
            float e0 = __expf(dl * a0), e1 = __expf(dl * a1);
            h0 = fmaf(e0, h0, coef * bc_s[t][n + 0]);
            h1 = fmaf(e1, h1, coef * bc_s[t][n + 1]);
            float y = h0 * bc_s[t][16 + n + 0] + h1 * bc_s[t][16 + n + 1];
            y += __shfl_xor_sync(0xffffffffu, y, 1);
            y += __shfl_xor_sync(0xffffffffu, y, 2);
            y += __shfl_xor_sync(0xffffffffu, y, 4);
            if (sg == 0) {
                float yt = fmaf(dd, xv, y);
                float zv = z_s[t][c];
                float sz = __fdividef(zv, 1.f + __expf(-zv));  // silu(z)
                y_s[t][c] = yt * sz;
            }
        }
        __syncthreads();

        #pragma unroll
        for (int i = tid; i < 1024; i += 256) {
            int t = i >> 5;
            ys[(rb + t0 + t) * DI + d0 + cs] = tf32r(y_s[t][cs]);
        }
        // safe without an extra sync: staging writes x/dl/z/bc only and the
        // post-staging __syncthreads orders them before the step loop; the
        // writeout reads y_s only, which staging never touches.
    }
}

// =====================================================================
// launcher
// =====================================================================
extern "C" void kernel_launch(void* const* d_in, const int* in_sizes, int n_in,
                              void* d_out, int out_size)
{
    const float* x    = (const float*)d_in[0];
    const float* ln_g = (const float*)d_in[1];
    const float* ln_b = (const float*)d_in[2];
    const float* Win  = (const float*)d_in[3];   // (3072, 768)
    const float* cw   = (const float*)d_in[4];   // (1536, 1, 4)
    const float* cb   = (const float*)d_in[5];   // (1536,)
    const float* Wxp  = (const float*)d_in[6];   // (33, 1536)
    const float* dtw  = (const float*)d_in[7];   // (1536, 1)
    const float* dtb  = (const float*)d_in[8];   // (1536,)
    const float* Alog = (const float*)d_in[9];   // (1536, 16)
    const float* Dv   = (const float*)d_in[10];  // (1536,)
    const float* Wout = (const float*)d_in[11];  // (768, 1536)
    float* out = (float*)d_out;

    float *xn, *xz, *xbc, *xp, *ys, *wa, *wb;
    cudaGetSymbolAddress((void**)&xn,  g_xn);
    cudaGetSymbolAddress((void**)&xz,  g_xz);
    cudaGetSymbolAddress((void**)&xbc, g_xbc);
    cudaGetSymbolAddress((void**)&xp,  g_xp);
    cudaGetSymbolAddress((void**)&ys,  g_ys);
    cudaGetSymbolAddress((void**)&wa,  g_wa);
    cudaGetSymbolAddress((void**)&wb,  g_wb);

    // 0) round weights to tf32 (RNA)
    {
        int n4a = (2 * DI * DM) / 4;
        round_tf32_kernel<<<(n4a + 255) / 256, 256>>>(Win, wa, n4a);
        int n4b = (DM * DI) / 4;
        round_tf32_kernel<<<(n4b + 255) / 256, 256>>>(Wout, wb, n4b);
    }

    // 1) LayerNorm (tf32-rounded output)
    ln_kernel<<<NROWS, 256>>>(x, ln_g, ln_b, xn);

    // 2) in_proj: xz = xn @ Win^T   (16384 x 3072, K=768) — tensor cores
    tf32_gemm_nt<false><<<dim3(3072 / 128, NROWS / 128), 256>>>(
        xn, wa, nullptr, xz, NROWS, 2 * DI, DM);

    // 3) fused conv+silu+x_proj (writes xbc + xp; no delta tensor)
    xproj_kernel<<<NROWS / 8, 256>>>(xz, cw, cb, Wxp, xbc, xp);

    // 4) selective scan (delta computed inline from xp0/dtw/dtb)
    scan_kernel<<<dim3(DI / 32, B_SZ), 256>>>(xbc, xz, xp, dtw, dtb, Alog, Dv, ys);

    // 5) out_proj + residual: out = ys @ Wout^T + x — tensor cores
    tf32_gemm_nt<true><<<dim3(DM / 128, NROWS / 128), 256>>>(
        ys, wb, x, out, NROWS, DM, DI);
}